// round 3
// baseline (speedup 1.0000x reference)
#include <cuda_runtime.h>
#include <math_constants.h>

// Fixed problem shape: B=16, R=Hr*Wr=4096, Q=Hq*Wq=1024
#define R 4096
#define Q 1024
#define MAXB 16
#define WARPS 8
#define TROWS 8
#define ROWS_PER_BLK (WARPS * TROWS)   // 64
#define BPB (R / ROWS_PER_BLK)         // 64 blocks per batch
#define K 48                           // candidate slots per row
#define DX 0.75f                       // candidate threshold below row max (x units)

// Scratch (static device memory; no runtime allocation)
__device__ float4 g_hdr[MAXB * R];                    // per row: (rowsum, rowmax, cnt, -)
__device__ float2 g_cand[(size_t)MAXB * R * K];       // per row: up to K (x, q) pairs
__device__ float  g_part[MAXB * BPB * Q];             // partial column sums
__device__ float  g_creflog[MAXB * Q];                // log column sums
__device__ unsigned int g_cminbits[MAXB];             // per-batch min Cref (ordered bits)

// order-preserving float<->uint maps for atomicMin on floats
__device__ __forceinline__ unsigned int f2ord(float f) {
    unsigned int u = __float_as_uint(f);
    return (u & 0x80000000u) ? ~u : (u | 0x80000000u);
}
__device__ __forceinline__ float ord2f(unsigned int u) {
    return __uint_as_float((u & 0x80000000u) ? (u & 0x7FFFFFFFu) : ~u);
}

// ---------------------------------------------------------------------------
// Kernel 1: single streaming read of x.
// Warp-per-row (8 rows each, 64 rows/block). Per row:
//   pass A: accumulate exp(ar*x) into per-lane column partials, row sum of
//           exp(aq*x) (reuses exp when ar==aq), running row max.
//   pass B: re-read row from L1, emit candidates x >= rowmax - DX.
// Block epilogue: merge per-lane column partials in smem, write one partial
// column-sum vector per block.
// ---------------------------------------------------------------------------
__global__ __launch_bounds__(256, 3) void qatm_k1(
    const float* __restrict__ x,
    const float* __restrict__ cr,
    const float* __restrict__ cq)
{
    __shared__ float s_col[Q];
    __shared__ int s_cnt[WARPS];

    if (blockIdx.x == 0 && threadIdx.x < MAXB)
        g_cminbits[threadIdx.x] = 0xFFFFFFFFu;   // +inf in ordered encoding

    const int wid  = threadIdx.x >> 5;
    const int lane = threadIdx.x & 31;
    const int b    = blockIdx.x / BPB;
    const int blkb = blockIdx.x - b * BPB;
    const int rowbase = b * R + blkb * ROWS_PER_BLK;

    const float ar = cr[0];
    const float aq = cq[0];
    const bool same = (ar == aq);

    for (int i = threadIdx.x; i < Q; i += 256) s_col[i] = 0.f;
    __syncthreads();

    float colacc[8][4];
    #pragma unroll
    for (int i = 0; i < 8; ++i)
        #pragma unroll
        for (int c = 0; c < 4; ++c) colacc[i][c] = 0.f;

    for (int t = 0; t < TROWS; ++t) {
        const int row = rowbase + wid * TROWS + t;
        const float4* p = reinterpret_cast<const float4*>(x + (size_t)row * Q) + lane;

        float rs = 0.f;
        float mx = -CUDART_INF_F;

        #pragma unroll
        for (int it = 0; it < 8; ++it) {
            float4 v = p[it * 32];
            float e0 = __expf(ar * v.x);
            float e1 = __expf(ar * v.y);
            float e2 = __expf(ar * v.z);
            float e3 = __expf(ar * v.w);
            colacc[it][0] += e0; colacc[it][1] += e1;
            colacc[it][2] += e2; colacc[it][3] += e3;
            if (same) {
                rs += (e0 + e1) + (e2 + e3);
            } else {
                rs += __expf(aq * v.x) + __expf(aq * v.y)
                    + __expf(aq * v.z) + __expf(aq * v.w);
            }
            mx = fmaxf(mx, fmaxf(fmaxf(v.x, v.y), fmaxf(v.z, v.w)));
        }

        #pragma unroll
        for (int o = 16; o > 0; o >>= 1) {
            rs += __shfl_xor_sync(0xFFFFFFFFu, rs, o);
            mx = fmaxf(mx, __shfl_xor_sync(0xFFFFFFFFu, mx, o));
        }

        if (lane == 0) s_cnt[wid] = 0;
        __syncwarp();
        asm volatile("" ::: "memory");   // force pass-B reloads (L1 hits)

        const float thr = mx - DX;
        float2* cbase = g_cand + (size_t)row * K;

        #pragma unroll
        for (int it = 0; it < 8; ++it) {
            float4 v = p[it * 32];
            int q0 = 4 * (it * 32 + lane);
            if (v.x >= thr) { int s = atomicAdd(&s_cnt[wid], 1); if (s < K) cbase[s] = make_float2(v.x, __int_as_float(q0));     }
            if (v.y >= thr) { int s = atomicAdd(&s_cnt[wid], 1); if (s < K) cbase[s] = make_float2(v.y, __int_as_float(q0 + 1)); }
            if (v.z >= thr) { int s = atomicAdd(&s_cnt[wid], 1); if (s < K) cbase[s] = make_float2(v.z, __int_as_float(q0 + 2)); }
            if (v.w >= thr) { int s = atomicAdd(&s_cnt[wid], 1); if (s < K) cbase[s] = make_float2(v.w, __int_as_float(q0 + 3)); }
        }
        __syncwarp();
        if (lane == 0)
            g_hdr[row] = make_float4(rs, mx, __int_as_float(s_cnt[wid]), 0.f);
        __syncwarp();
    }

    // merge per-lane column partials
    #pragma unroll
    for (int it = 0; it < 8; ++it)
        #pragma unroll
        for (int c = 0; c < 4; ++c)
            atomicAdd(&s_col[4 * (it * 32 + lane) + c], colacc[it][c]);
    __syncthreads();

    float4* gp = reinterpret_cast<float4*>(g_part + (size_t)blockIdx.x * Q);
    gp[threadIdx.x] = reinterpret_cast<const float4*>(s_col)[threadIdx.x];
}

// ---------------------------------------------------------------------------
// Kernel 2: reduce BPB partials per column -> Cref = log(colsum); per-batch min.
// grid = B*4 blocks, thread-per-column.
// ---------------------------------------------------------------------------
__global__ __launch_bounds__(256) void qatm_cred()
{
    __shared__ float s_min[256];
    const int b   = blockIdx.x >> 2;
    const int col = ((blockIdx.x & 3) << 8) + threadIdx.x;

    const float* p = g_part + (size_t)b * BPB * Q + col;
    float s = 0.f;
    #pragma unroll 8
    for (int c = 0; c < BPB; ++c) s += p[(size_t)c * Q];

    float lg = __logf(s);
    g_creflog[b * Q + col] = lg;

    s_min[threadIdx.x] = lg;
    __syncthreads();
    #pragma unroll
    for (int o = 128; o > 0; o >>= 1) {
        if (threadIdx.x < o)
            s_min[threadIdx.x] = fminf(s_min[threadIdx.x], s_min[threadIdx.x + o]);
        __syncthreads();
    }
    if (threadIdx.x == 0)
        atomicMin(&g_cminbits[b], f2ord(s_min[0]));
}

// ---------------------------------------------------------------------------
// Kernel 3: per-row output from candidates. Exactness check:
// unstored terms < cc*(rowmax - DX) - Cmin. If candidate max doesn't dominate
// that bound (or buffer overflowed), fall back to an exact full-row rescan.
// ---------------------------------------------------------------------------
__global__ __launch_bounds__(256) void qatm_p2(
    const float* __restrict__ x,
    const float* __restrict__ cr,
    const float* __restrict__ cq,
    float* __restrict__ out)
{
    __shared__ __align__(16) float s_clog[Q];

    const int wid  = threadIdx.x >> 5;
    const int lane = threadIdx.x & 31;
    const int row0 = blockIdx.x * 8;
    const int b    = row0 >> 12;

    reinterpret_cast<float4*>(s_clog)[threadIdx.x] =
        reinterpret_cast<const float4*>(g_creflog + (size_t)b * Q)[threadIdx.x];
    __syncthreads();

    const float cc    = cr[0] + cq[0];
    const float cminf = ord2f(g_cminbits[b]);

    const int row = row0 + wid;
    float4 hdr = g_hdr[row];
    const float rs = hdr.x;
    const float xm = hdr.y;
    const int cnt = __float_as_int(hdr.z);

    float cmax = -CUDART_INF_F;
    bool exact = false;

    if (cnt <= K) {
        const float2* cb = g_cand + (size_t)row * K;
        for (int i = lane; i < cnt; i += 32) {
            float2 f2 = cb[i];
            cmax = fmaxf(cmax, fmaf(cc, f2.x, -s_clog[__float_as_int(f2.y)]));
        }
        #pragma unroll
        for (int o = 16; o > 0; o >>= 1)
            cmax = fmaxf(cmax, __shfl_xor_sync(0xFFFFFFFFu, cmax, o));
        const float bound = cc * (xm - DX) - cminf + 1e-3f;  // sup of unstored + FP margin
        exact = (cmax >= bound);
    }

    if (!exact) {   // warp-uniform, statistically ~never taken
        const float4* p = reinterpret_cast<const float4*>(x + (size_t)row * Q);
        cmax = -CUDART_INF_F;
        #pragma unroll
        for (int it = 0; it < 8; ++it) {
            int q4 = it * 32 + lane;
            float4 v = p[q4];
            float4 cg = reinterpret_cast<const float4*>(s_clog)[q4];
            float m0 = fmaxf(fmaf(cc, v.x, -cg.x), fmaf(cc, v.y, -cg.y));
            float m1 = fmaxf(fmaf(cc, v.z, -cg.z), fmaf(cc, v.w, -cg.w));
            cmax = fmaxf(cmax, fmaxf(m0, m1));
        }
        #pragma unroll
        for (int o = 16; o > 0; o >>= 1)
            cmax = fmaxf(cmax, __shfl_xor_sync(0xFFFFFFFFu, cmax, o));
    }

    if (lane == 0)
        out[row] = __expf(0.5f * (cmax - __logf(rs)));
}

// ---------------------------------------------------------------------------
extern "C" void kernel_launch(void* const* d_in, const int* in_sizes, int n_in,
                              void* d_out, int out_size)
{
    const float* x  = (const float*)d_in[0];
    const float* cr = (const float*)d_in[1];
    const float* cq = (const float*)d_in[2];
    float* out = (float*)d_out;

    const int B = in_sizes[0] / (R * Q);   // 16

    qatm_k1<<<B * BPB, 256>>>(x, cr, cq);
    qatm_cred<<<B * 4, 256>>>();
    qatm_p2<<<B * R / 8, 256>>>(x, cr, cq, out);
}

// round 4
// speedup vs baseline: 1.4187x; 1.4187x over previous
#include <cuda_runtime.h>
#include <math_constants.h>

// Fixed problem shape: B=16, R=Hr*Wr=4096, Q=Hq*Wq=1024
#define R 4096
#define Q 1024
#define MAXB 16
#define RCHUNK 64
#define NCHUNK (R / RCHUNK)     // 64 chunks per batch
#define NBLK 32                 // 32 column-blocks of 32 columns each

// Static device scratch
__device__ float  g_part[NCHUNK * MAXB * Q];          // 4 MB partial column sums
__device__ float  g_creflog[MAXB * Q];                // 64 KB log column sums
__device__ float2 g_cblk[MAXB * NBLK];                // per-32col (Cmin, Cmax)
__device__ float  g_bm[(size_t)MAXB * R * NBLK];      // 8 MB per-row 32-col maxes
__device__ float  g_rs[MAXB * R];                     // 256 KB row sums of exp(aq*x)

// ---------------------------------------------------------------------------
// Pass 1: stream x once per 64-row chunk. Thread t owns columns 4t..4t+3.
// Produces: partial column sums (exp(ar*x)), per-row sums of exp(aq*x),
// and per-row per-32-column maxes of x.
// ---------------------------------------------------------------------------
__global__ __launch_bounds__(256) void qatm_pass1(
    const float* __restrict__ x,
    const float* __restrict__ cr,
    const float* __restrict__ cq)
{
    __shared__ float s_bm[RCHUNK * NBLK];   // 8 KB: [row][j]
    __shared__ float s_rs[RCHUNK * 8];      // 2 KB: [row][warp]

    const int b    = blockIdx.x >> 6;
    const int c    = blockIdx.x & (NCHUNK - 1);
    const int t    = threadIdx.x;
    const int wid  = t >> 5;
    const int lane = t & 31;
    const int g    = t >> 3;                // column-block 0..31 owned by this thread

    const float ar = cr[0];
    const float aq = cq[0];
    const bool same = (ar == aq);

    const float4* p = reinterpret_cast<const float4*>(
        x + ((size_t)b * R + (size_t)c * RCHUNK) * Q) + t;

    float4 acc = make_float4(0.f, 0.f, 0.f, 0.f);

    #pragma unroll 1
    for (int r = 0; r < RCHUNK; r += 4) {
        float4 v0 = p[0 * (Q / 4)];
        float4 v1 = p[1 * (Q / 4)];
        float4 v2 = p[2 * (Q / 4)];
        float4 v3 = p[3 * (Q / 4)];
        p += 4 * (Q / 4);

        #pragma unroll
        for (int k = 0; k < 4; ++k) {
            float4 v = (k == 0) ? v0 : (k == 1) ? v1 : (k == 2) ? v2 : v3;

            float e0 = __expf(ar * v.x);
            float e1 = __expf(ar * v.y);
            float e2 = __expf(ar * v.z);
            float e3 = __expf(ar * v.w);
            acc.x += e0; acc.y += e1; acc.z += e2; acc.w += e3;

            float rs;
            if (same) {
                rs = (e0 + e1) + (e2 + e3);
            } else {
                rs = __expf(aq * v.x) + __expf(aq * v.y)
                   + __expf(aq * v.z) + __expf(aq * v.w);
            }
            // warp sum (row covers 128 cols per warp)
            #pragma unroll
            for (int o = 16; o > 0; o >>= 1)
                rs += __shfl_xor_sync(0xFFFFFFFFu, rs, o);

            // 8-lane group max (32 columns)
            float mk = fmaxf(fmaxf(v.x, v.y), fmaxf(v.z, v.w));
            mk = fmaxf(mk, __shfl_xor_sync(0xFFFFFFFFu, mk, 4));
            mk = fmaxf(mk, __shfl_xor_sync(0xFFFFFFFFu, mk, 2));
            mk = fmaxf(mk, __shfl_xor_sync(0xFFFFFFFFu, mk, 1));

            if ((lane & 7) == 0) s_bm[(r + k) * NBLK + g] = mk;
            if (lane == 0)       s_rs[(r + k) * 8 + wid] = rs;
        }
    }
    __syncthreads();

    // partial column sums (same layout as R1: [chunk][b][col])
    reinterpret_cast<float4*>(g_part + (size_t)c * (MAXB * Q) + (size_t)b * Q)[t] = acc;

    // row sums: threads 0..63
    if (t < RCHUNK) {
        const float* sr = s_rs + t * 8;
        float s = ((sr[0] + sr[1]) + (sr[2] + sr[3]))
                + ((sr[4] + sr[5]) + (sr[6] + sr[7]));
        g_rs[b * R + c * RCHUNK + t] = s;
    }

    // block maxes: 64 rows * 32 = 512 float4
    float4* gbm = reinterpret_cast<float4*>(
        g_bm + ((size_t)b * R + (size_t)c * RCHUNK) * NBLK);
    const float4* sb = reinterpret_cast<const float4*>(s_bm);
    gbm[t]       = sb[t];
    gbm[t + 256] = sb[t + 256];
}

// ---------------------------------------------------------------------------
// Kernel 2: reduce NCHUNK partials per column -> Cref = log(colsum);
// per-32-column (Cmin, Cmax). grid = B*4 blocks (256 cols each).
// ---------------------------------------------------------------------------
__global__ __launch_bounds__(256) void qatm_cred()
{
    const int b    = blockIdx.x >> 2;
    const int col  = ((blockIdx.x & 3) << 8) + threadIdx.x;
    const int lane = threadIdx.x & 31;

    const float* p = g_part + (size_t)b * Q + col;
    float s = 0.f;
    #pragma unroll 8
    for (int c = 0; c < NCHUNK; ++c)
        s += p[(size_t)c * (MAXB * Q)];

    float lg = __logf(s);
    g_creflog[b * Q + col] = lg;

    float mn = lg, mx = lg;
    #pragma unroll
    for (int o = 16; o > 0; o >>= 1) {
        mn = fminf(mn, __shfl_xor_sync(0xFFFFFFFFu, mn, o));
        mx = fmaxf(mx, __shfl_xor_sync(0xFFFFFFFFu, mx, o));
    }
    if (lane == 0)
        g_cblk[b * NBLK + (col >> 5)] = make_float2(mn, mx);
}

// ---------------------------------------------------------------------------
// Pass 2: warp per row. Exact branch-and-bound over 32 column blocks:
//   ub_j = cc*bm_j - Cmin_j,  lb_j = cc*bm_j - Cmax_j,  lb = max_j lb_j.
// Re-read x only for blocks with ub_j >= lb; exact max over those.
// ---------------------------------------------------------------------------
__global__ __launch_bounds__(256) void qatm_p2(
    const float* __restrict__ x,
    const float* __restrict__ cr,
    const float* __restrict__ cq,
    float* __restrict__ out)
{
    __shared__ __align__(16) float s_clog[Q];
    __shared__ float2 s_cb[NBLK];

    const int wid  = threadIdx.x >> 5;
    const int lane = threadIdx.x & 31;
    const int row0 = blockIdx.x * 8;
    const int b    = row0 >> 12;

    reinterpret_cast<float4*>(s_clog)[threadIdx.x] =
        reinterpret_cast<const float4*>(g_creflog + (size_t)b * Q)[threadIdx.x];
    if (threadIdx.x < NBLK) s_cb[threadIdx.x] = g_cblk[b * NBLK + threadIdx.x];
    __syncthreads();

    const float cc = cr[0] + cq[0];

    const int row = row0 + wid;
    const float bm  = g_bm[(size_t)row * NBLK + lane];
    const float2 cb = s_cb[lane];
    const float ub  = fmaf(cc, bm, -cb.x);
    float lb        = fmaf(cc, bm, -cb.y);

    #pragma unroll
    for (int o = 16; o > 0; o >>= 1)
        lb = fmaxf(lb, __shfl_xor_sync(0xFFFFFFFFu, lb, o));

    unsigned mask = __ballot_sync(0xFFFFFFFFu, ub >= lb);

    const float* px = x + (size_t)row * Q;
    float m = -CUDART_INF_F;
    while (mask) {
        int j = __ffs(mask) - 1;
        mask &= mask - 1;
        int q = j * 32 + lane;
        float v = __ldcs(px + q);
        m = fmaxf(m, fmaf(cc, v, -s_clog[q]));
    }
    #pragma unroll
    for (int o = 16; o > 0; o >>= 1)
        m = fmaxf(m, __shfl_xor_sync(0xFFFFFFFFu, m, o));

    if (lane == 0)
        out[row] = __expf(0.5f * (m - __logf(g_rs[row])));
}

// ---------------------------------------------------------------------------
extern "C" void kernel_launch(void* const* d_in, const int* in_sizes, int n_in,
                              void* d_out, int out_size)
{
    const float* x  = (const float*)d_in[0];
    const float* cr = (const float*)d_in[1];
    const float* cq = (const float*)d_in[2];
    float* out = (float*)d_out;

    const int B = in_sizes[0] / (R * Q);   // 16

    qatm_pass1<<<B * NCHUNK, 256>>>(x, cr, cq);
    qatm_cred<<<B * 4, 256>>>();
    qatm_p2<<<B * R / 8, 256>>>(x, cr, cq, out);
}

// round 5
// speedup vs baseline: 1.5917x; 1.1219x over previous
#include <cuda_runtime.h>
#include <math_constants.h>

// Fixed problem shape: B=16, R=Hr*Wr=4096, Q=Hq*Wq=1024
#define R 4096
#define Q 1024
#define MAXB 16
#define RCHUNK 64
#define NCHUNK (R / RCHUNK)     // 64 chunks per batch
#define NBLK 32                 // 32 column-blocks of 32 columns each

// Static device scratch
__device__ float  g_part[NCHUNK * MAXB * Q];          // 4 MB partial column sums
__device__ float  g_creflog[MAXB * Q];                // 64 KB log column sums
__device__ float2 g_cblk[MAXB * NBLK];                // per-32col (Cmin, Cmax)
__device__ float  g_bm[(size_t)MAXB * R * NBLK];      // 8 MB per-row 32-col maxes
__device__ float  g_rs[MAXB * R];                     // 256 KB row sums of exp(aq*x)

// ---------------------------------------------------------------------------
// Pass 1 (unchanged from R4 — measured 48.6us @ 68.8% DRAM):
// stream x once per 64-row chunk; thread t owns columns 4t..4t+3.
// Produces partial column sums of exp(ar*x), per-row sums of exp(aq*x),
// and per-row per-32-column maxes of x.
// ---------------------------------------------------------------------------
__global__ __launch_bounds__(256) void qatm_pass1(
    const float* __restrict__ x,
    const float* __restrict__ cr,
    const float* __restrict__ cq)
{
    __shared__ float s_bm[RCHUNK * NBLK];   // 8 KB: [row][j]
    __shared__ float s_rs[RCHUNK * 8];      // 2 KB: [row][warp]

    const int b    = blockIdx.x >> 6;
    const int c    = blockIdx.x & (NCHUNK - 1);
    const int t    = threadIdx.x;
    const int wid  = t >> 5;
    const int lane = t & 31;
    const int g    = t >> 3;                // column-block 0..31 owned by this thread

    const float ar = cr[0];
    const float aq = cq[0];
    const bool same = (ar == aq);

    const float4* p = reinterpret_cast<const float4*>(
        x + ((size_t)b * R + (size_t)c * RCHUNK) * Q) + t;

    float4 acc = make_float4(0.f, 0.f, 0.f, 0.f);

    #pragma unroll 1
    for (int r = 0; r < RCHUNK; r += 4) {
        float4 v0 = p[0 * (Q / 4)];
        float4 v1 = p[1 * (Q / 4)];
        float4 v2 = p[2 * (Q / 4)];
        float4 v3 = p[3 * (Q / 4)];
        p += 4 * (Q / 4);

        #pragma unroll
        for (int k = 0; k < 4; ++k) {
            float4 v = (k == 0) ? v0 : (k == 1) ? v1 : (k == 2) ? v2 : v3;

            float e0 = __expf(ar * v.x);
            float e1 = __expf(ar * v.y);
            float e2 = __expf(ar * v.z);
            float e3 = __expf(ar * v.w);
            acc.x += e0; acc.y += e1; acc.z += e2; acc.w += e3;

            float rs;
            if (same) {
                rs = (e0 + e1) + (e2 + e3);
            } else {
                rs = __expf(aq * v.x) + __expf(aq * v.y)
                   + __expf(aq * v.z) + __expf(aq * v.w);
            }
            // warp sum (row covers 128 cols per warp)
            #pragma unroll
            for (int o = 16; o > 0; o >>= 1)
                rs += __shfl_xor_sync(0xFFFFFFFFu, rs, o);

            // 8-lane group max (32 columns)
            float mk = fmaxf(fmaxf(v.x, v.y), fmaxf(v.z, v.w));
            mk = fmaxf(mk, __shfl_xor_sync(0xFFFFFFFFu, mk, 4));
            mk = fmaxf(mk, __shfl_xor_sync(0xFFFFFFFFu, mk, 2));
            mk = fmaxf(mk, __shfl_xor_sync(0xFFFFFFFFu, mk, 1));

            if ((lane & 7) == 0) s_bm[(r + k) * NBLK + g] = mk;
            if (lane == 0)       s_rs[(r + k) * 8 + wid] = rs;
        }
    }
    __syncthreads();

    // partial column sums ([chunk][b][col])
    reinterpret_cast<float4*>(g_part + (size_t)c * (MAXB * Q) + (size_t)b * Q)[t] = acc;

    // row sums: threads 0..63
    if (t < RCHUNK) {
        const float* sr = s_rs + t * 8;
        float s = ((sr[0] + sr[1]) + (sr[2] + sr[3]))
                + ((sr[4] + sr[5]) + (sr[6] + sr[7]));
        g_rs[b * R + c * RCHUNK + t] = s;
    }

    // block maxes: 64 rows * 32 = 512 float4
    float4* gbm = reinterpret_cast<float4*>(
        g_bm + ((size_t)b * R + (size_t)c * RCHUNK) * NBLK);
    const float4* sb = reinterpret_cast<const float4*>(s_bm);
    gbm[t]       = sb[t];
    gbm[t + 256] = sb[t + 256];
}

// ---------------------------------------------------------------------------
// Kernel 2 (unchanged): Cref = log(colsum); per-32-column (Cmin, Cmax).
// ---------------------------------------------------------------------------
__global__ __launch_bounds__(256) void qatm_cred()
{
    const int b    = blockIdx.x >> 2;
    const int col  = ((blockIdx.x & 3) << 8) + threadIdx.x;
    const int lane = threadIdx.x & 31;

    const float* p = g_part + (size_t)b * Q + col;
    float s = 0.f;
    #pragma unroll 8
    for (int c = 0; c < NCHUNK; ++c)
        s += p[(size_t)c * (MAXB * Q)];

    float lg = __logf(s);
    g_creflog[b * Q + col] = lg;

    float mn = lg, mx = lg;
    #pragma unroll
    for (int o = 16; o > 0; o >>= 1) {
        mn = fminf(mn, __shfl_xor_sync(0xFFFFFFFFu, mn, o));
        mx = fmaxf(mx, __shfl_xor_sync(0xFFFFFFFFu, mx, o));
    }
    if (lane == 0)
        g_cblk[b * NBLK + (col >> 5)] = make_float2(mn, mx);
}

// ---------------------------------------------------------------------------
// Pass 2: warp per row, self-refining exact branch-and-bound.
//   ub_j = cc*bm_j - Cmin_j  (true upper bound of block j)
//   j*   = argmax ub_j; m* = EXACT max over block j* (one 128B read)
//   scan only blocks with ub_j >= m*.
// No smem staging: Cref table (64KB) is L2-resident, read via __ldg.
// ---------------------------------------------------------------------------
__global__ __launch_bounds__(256) void qatm_p2(
    const float* __restrict__ x,
    const float* __restrict__ cr,
    const float* __restrict__ cq,
    float* __restrict__ out)
{
    const int wid  = threadIdx.x >> 5;
    const int lane = threadIdx.x & 31;
    const int row  = blockIdx.x * 8 + wid;
    const int b    = row >> 12;

    const float cc = cr[0] + cq[0];

    const float bm  = g_bm[(size_t)row * NBLK + lane];
    const float2 cb = __ldg(&g_cblk[b * NBLK + lane]);
    const float ub  = fmaf(cc, bm, -cb.x);

    // j* = argmax_j ub_j
    float ubmax = ub;
    #pragma unroll
    for (int o = 16; o > 0; o >>= 1)
        ubmax = fmaxf(ubmax, __shfl_xor_sync(0xFFFFFFFFu, ubmax, o));
    const unsigned win = __ballot_sync(0xFFFFFFFFu, ub == ubmax);
    const int jstar = __ffs(win) - 1;

    const float* px = x + (size_t)row * Q;
    const float* cl = g_creflog + (size_t)b * Q;

    // exact max over block j* -> tight lower bound m
    int q = jstar * 32 + lane;
    float m = fmaf(cc, __ldcs(px + q), -__ldg(cl + q));
    #pragma unroll
    for (int o = 16; o > 0; o >>= 1)
        m = fmaxf(m, __shfl_xor_sync(0xFFFFFFFFu, m, o));

    // survivors: blocks whose upper bound can still beat m
    unsigned mask = __ballot_sync(0xFFFFFFFFu, ub >= m) & ~(1u << jstar);

    while (mask) {
        int j = __ffs(mask) - 1;
        mask &= mask - 1;
        q = j * 32 + lane;
        m = fmaxf(m, fmaf(cc, __ldcs(px + q), -__ldg(cl + q)));
    }
    #pragma unroll
    for (int o = 16; o > 0; o >>= 1)
        m = fmaxf(m, __shfl_xor_sync(0xFFFFFFFFu, m, o));

    if (lane == 0)
        out[row] = __expf(0.5f * (m - __logf(g_rs[row])));
}

// ---------------------------------------------------------------------------
extern "C" void kernel_launch(void* const* d_in, const int* in_sizes, int n_in,
                              void* d_out, int out_size)
{
    const float* x  = (const float*)d_in[0];
    const float* cr = (const float*)d_in[1];
    const float* cq = (const float*)d_in[2];
    float* out = (float*)d_out;

    const int B = in_sizes[0] / (R * Q);   // 16

    qatm_pass1<<<B * NCHUNK, 256>>>(x, cr, cq);
    qatm_cred<<<B * 4, 256>>>();
    qatm_p2<<<B * R / 8, 256>>>(x, cr, cq, out);
}

// round 6
// speedup vs baseline: 1.7597x; 1.1055x over previous
#include <cuda_runtime.h>
#include <math_constants.h>

// Fixed problem shape: B=16, R=Hr*Wr=4096, Q=Hq*Wq=1024
#define R 4096
#define Q 1024
#define MAXB 16
#define RCHUNK 64
#define NCHUNK (R / RCHUNK)     // 64 chunks per batch
#define NBLK 32                 // 32 column-blocks of 32 columns each

// Static device scratch
__device__ float  g_part[NCHUNK * MAXB * Q];                 // 4 MB partial column sums
__device__ float  g_creflog[MAXB * Q];                        // 64 KB log column sums
__device__ float  g_cmin[MAXB * NBLK];                        // per-32col min Cref
__device__ float  g_bm[(size_t)MAXB * R * NBLK];              // 8 MB per-row 32-col maxes
__device__ __align__(16) unsigned char g_bi[(size_t)MAXB * R * NBLK];  // 2 MB witness idx
__device__ float  g_rs[MAXB * R];                             // row sums of exp(aq*x)

// ---------------------------------------------------------------------------
// Pass 1: stream x once per 64-row chunk; thread t owns columns 4t..4t+3.
// Produces: partial column sums of exp(ar*x), per-row sums of exp(aq*x),
// per-row per-32-column maxes of x AND the witness index of each max.
// ---------------------------------------------------------------------------
__global__ __launch_bounds__(256) void qatm_pass1(
    const float* __restrict__ x,
    const float* __restrict__ cr,
    const float* __restrict__ cq)
{
    __shared__ float s_bm[RCHUNK * NBLK];                     // 8 KB [row][j]
    __shared__ __align__(8) unsigned char s_bi[RCHUNK * NBLK];// 2 KB [row][j]
    __shared__ float s_rs[RCHUNK * 8];                        // 2 KB [row][warp]

    const int b    = blockIdx.x >> 6;
    const int c    = blockIdx.x & (NCHUNK - 1);
    const int t    = threadIdx.x;
    const int wid  = t >> 5;
    const int lane = t & 31;
    const int g    = t >> 3;                 // column-block 0..31 owned by thread
    const int l8   = 4 * (lane & 7);         // base idx of this thread within block

    const float ar = cr[0];
    const float aq = cq[0];
    const bool same = (ar == aq);

    const float4* p = reinterpret_cast<const float4*>(
        x + ((size_t)b * R + (size_t)c * RCHUNK) * Q) + t;

    float4 acc = make_float4(0.f, 0.f, 0.f, 0.f);

    #pragma unroll 1
    for (int r = 0; r < RCHUNK; r += 4) {
        float4 v0 = p[0 * (Q / 4)];
        float4 v1 = p[1 * (Q / 4)];
        float4 v2 = p[2 * (Q / 4)];
        float4 v3 = p[3 * (Q / 4)];
        p += 4 * (Q / 4);

        #pragma unroll
        for (int k = 0; k < 4; ++k) {
            float4 v = (k == 0) ? v0 : (k == 1) ? v1 : (k == 2) ? v2 : v3;

            float e0 = __expf(ar * v.x);
            float e1 = __expf(ar * v.y);
            float e2 = __expf(ar * v.z);
            float e3 = __expf(ar * v.w);
            acc.x += e0; acc.y += e1; acc.z += e2; acc.w += e3;

            float rs;
            if (same) {
                rs = (e0 + e1) + (e2 + e3);
            } else {
                rs = __expf(aq * v.x) + __expf(aq * v.y)
                   + __expf(aq * v.z) + __expf(aq * v.w);
            }
            #pragma unroll
            for (int o = 16; o > 0; o >>= 1)
                rs += __shfl_xor_sync(0xFFFFFFFFu, rs, o);

            // 8-lane group max (32 columns) — exact propagation via fmaxf
            float mk = fmaxf(fmaxf(v.x, v.y), fmaxf(v.z, v.w));
            mk = fmaxf(mk, __shfl_xor_sync(0xFFFFFFFFu, mk, 4));
            mk = fmaxf(mk, __shfl_xor_sync(0xFFFFFFFFu, mk, 2));
            mk = fmaxf(mk, __shfl_xor_sync(0xFFFFFFFFu, mk, 1));

            // witness index: some lane's component equals mk exactly
            int idx = -1;
            if (v.x == mk) idx = l8;
            if (v.y == mk) idx = l8 + 1;
            if (v.z == mk) idx = l8 + 2;
            if (v.w == mk) idx = l8 + 3;
            if (idx >= 0) s_bi[(r + k) * NBLK + g] = (unsigned char)idx;

            if ((lane & 7) == 0) s_bm[(r + k) * NBLK + g] = mk;
            if (lane == 0)       s_rs[(r + k) * 8 + wid] = rs;
        }
    }
    __syncthreads();

    // partial column sums ([chunk][b][col])
    reinterpret_cast<float4*>(g_part + (size_t)c * (MAXB * Q) + (size_t)b * Q)[t] = acc;

    // row sums: threads 0..63
    if (t < RCHUNK) {
        const float* sr = s_rs + t * 8;
        float s = ((sr[0] + sr[1]) + (sr[2] + sr[3]))
                + ((sr[4] + sr[5]) + (sr[6] + sr[7]));
        g_rs[b * R + c * RCHUNK + t] = s;
    }

    // block maxes (8 KB) + witness indices (2 KB)
    const size_t rowbase = (size_t)b * R + (size_t)c * RCHUNK;
    float4* gbm = reinterpret_cast<float4*>(g_bm + rowbase * NBLK);
    const float4* sb = reinterpret_cast<const float4*>(s_bm);
    gbm[t]       = sb[t];
    gbm[t + 256] = sb[t + 256];
    reinterpret_cast<uint2*>(g_bi + rowbase * NBLK)[t] =
        reinterpret_cast<const uint2*>(s_bi)[t];
}

// ---------------------------------------------------------------------------
// Kernel 2: Cref = log(colsum); per-32-column Cmin.
// ---------------------------------------------------------------------------
__global__ __launch_bounds__(256) void qatm_cred()
{
    const int b    = blockIdx.x >> 2;
    const int col  = ((blockIdx.x & 3) << 8) + threadIdx.x;
    const int lane = threadIdx.x & 31;

    const float* p = g_part + (size_t)b * Q + col;
    float s = 0.f;
    #pragma unroll 8
    for (int c = 0; c < NCHUNK; ++c)
        s += p[(size_t)c * (MAXB * Q)];

    float lg = __logf(s);
    g_creflog[b * Q + col] = lg;

    float mn = lg;
    #pragma unroll
    for (int o = 16; o > 0; o >>= 1)
        mn = fminf(mn, __shfl_xor_sync(0xFFFFFFFFu, mn, o));
    if (lane == 0)
        g_cmin[b * NBLK + (col >> 5)] = mn;
}

// ---------------------------------------------------------------------------
// Pass 2: warp per row, witness-bound branch-and-bound with batched loads.
//   val_j = cc*bm_j - Cref[witness_j]   (exact achieved value, L2 gather only)
//   ub_j  = cc*bm_j - Cmin_j            (true upper bound)
//   lb    = max_j val_j; scan x only for blocks with ub_j > lb, 4 at a time.
// ---------------------------------------------------------------------------
__global__ __launch_bounds__(256) void qatm_p2(
    const float* __restrict__ x,
    const float* __restrict__ cr,
    const float* __restrict__ cq,
    float* __restrict__ out)
{
    const int wid  = threadIdx.x >> 5;
    const int lane = threadIdx.x & 31;
    const int row  = blockIdx.x * 8 + wid;
    const int b    = row >> 12;

    const float cc = cr[0] + cq[0];

    const float bm   = g_bm[(size_t)row * NBLK + lane];
    const int   bi   = (int)g_bi[(size_t)row * NBLK + lane];
    const float cmin = __ldg(&g_cmin[b * NBLK + lane]);
    const float* cl  = g_creflog + (size_t)b * Q;

    const float cwit = __ldg(cl + lane * 32 + bi);
    const float val  = fmaf(cc, bm, -cwit);   // exact value at block witness
    const float ub   = fmaf(cc, bm, -cmin);   // true block upper bound

    float lb = val;
    #pragma unroll
    for (int o = 16; o > 0; o >>= 1)
        lb = fmaxf(lb, __shfl_xor_sync(0xFFFFFFFFu, lb, o));

    unsigned mask = __ballot_sync(0xFFFFFFFFu, ub > lb);

    const float* px = x + (size_t)row * Q;
    float m = lb;

    while (mask) {
        // pull up to 4 survivor blocks, load independently (MLP 4-8)
        int j0 = __ffs(mask) - 1; mask &= mask - 1;
        int j1 = -1, j2 = -1, j3 = -1;
        if (mask) { j1 = __ffs(mask) - 1; mask &= mask - 1; }
        if (mask) { j2 = __ffs(mask) - 1; mask &= mask - 1; }
        if (mask) { j3 = __ffs(mask) - 1; mask &= mask - 1; }

        float m0 = fmaf(cc, __ldcs(px + j0 * 32 + lane), -__ldg(cl + j0 * 32 + lane));
        float m1 = (j1 >= 0) ? fmaf(cc, __ldcs(px + j1 * 32 + lane), -__ldg(cl + j1 * 32 + lane)) : -CUDART_INF_F;
        float m2 = (j2 >= 0) ? fmaf(cc, __ldcs(px + j2 * 32 + lane), -__ldg(cl + j2 * 32 + lane)) : -CUDART_INF_F;
        float m3 = (j3 >= 0) ? fmaf(cc, __ldcs(px + j3 * 32 + lane), -__ldg(cl + j3 * 32 + lane)) : -CUDART_INF_F;

        m = fmaxf(m, fmaxf(fmaxf(m0, m1), fmaxf(m2, m3)));
    }

    #pragma unroll
    for (int o = 16; o > 0; o >>= 1)
        m = fmaxf(m, __shfl_xor_sync(0xFFFFFFFFu, m, o));

    if (lane == 0)
        out[row] = __expf(0.5f * (m - __logf(g_rs[row])));
}

// ---------------------------------------------------------------------------
extern "C" void kernel_launch(void* const* d_in, const int* in_sizes, int n_in,
                              void* d_out, int out_size)
{
    const float* x  = (const float*)d_in[0];
    const float* cr = (const float*)d_in[1];
    const float* cq = (const float*)d_in[2];
    float* out = (float*)d_out;

    const int B = in_sizes[0] / (R * Q);   // 16

    qatm_pass1<<<B * NCHUNK, 256>>>(x, cr, cq);
    qatm_cred<<<B * 4, 256>>>();
    qatm_p2<<<B * R / 8, 256>>>(x, cr, cq, out);
}

// round 7
// speedup vs baseline: 1.8323x; 1.0413x over previous
#include <cuda_runtime.h>
#include <math_constants.h>

// Fixed problem shape: B=16, R=Hr*Wr=4096, Q=Hq*Wq=1024
#define R 4096
#define Q 1024
#define MAXB 16
#define RCHUNK 64
#define NCHUNK (R / RCHUNK)     // 64 chunks per batch
#define NBLK 32                 // 32 column-blocks of 32 columns each
#define LOG2E 1.4426950408889634f

// Static device scratch
__device__ float  g_part[NCHUNK * MAXB * Q];                 // 4 MB partial column sums
__device__ float  g_creflog[MAXB * Q];                        // 64 KB log column sums
__device__ float  g_cmin[MAXB * NBLK];                        // per-32col min Cref
__device__ float  g_bm[(size_t)MAXB * R * NBLK];              // 8 MB per-row 32-col maxes
__device__ __align__(16) unsigned char g_bi[(size_t)MAXB * R * NBLK];  // 2 MB witness idx
__device__ float  g_rs[MAXB * R];                             // row sums of exp(aq*x)

__device__ __forceinline__ float ex2f(float t) {
    float r;
    asm("ex2.approx.ftz.f32 %0, %1;" : "=f"(r) : "f"(t));
    return r;
}

// ---------------------------------------------------------------------------
// Pass 1: stream x once per 64-row chunk; thread t owns columns 4t..4t+3.
// exp via single FMUL (alpha*log2e folded) + ex2. Row sums reduced only to
// 8-lane (32-column) partials in the same butterfly as the block max; a
// 64-thread epilogue finishes them from smem.
// ---------------------------------------------------------------------------
__global__ __launch_bounds__(256) void qatm_pass1(
    const float* __restrict__ x,
    const float* __restrict__ cr,
    const float* __restrict__ cq)
{
    __shared__ float s_bm[RCHUNK * NBLK];                      // 8 KB [row][j]
    __shared__ float s_rs32[RCHUNK * NBLK];                    // 8 KB [row][j] partial rs
    __shared__ __align__(8) unsigned char s_bi[RCHUNK * NBLK]; // 2 KB [row][j]

    const int b    = blockIdx.x >> 6;
    const int c    = blockIdx.x & (NCHUNK - 1);
    const int t    = threadIdx.x;
    const int lane = t & 31;
    const int g    = t >> 3;                 // column-block 0..31 owned by thread
    const int l8   = 4 * (lane & 7);         // base idx of this thread within block

    const float ar  = cr[0];
    const float aq  = cq[0];
    const bool same = (ar == aq);
    const float arl = ar * LOG2E;
    const float aql = aq * LOG2E;

    const float4* p = reinterpret_cast<const float4*>(
        x + ((size_t)b * R + (size_t)c * RCHUNK) * Q) + t;

    float4 acc = make_float4(0.f, 0.f, 0.f, 0.f);

    #pragma unroll 1
    for (int r = 0; r < RCHUNK; r += 4) {
        float4 v0 = p[0 * (Q / 4)];
        float4 v1 = p[1 * (Q / 4)];
        float4 v2 = p[2 * (Q / 4)];
        float4 v3 = p[3 * (Q / 4)];
        p += 4 * (Q / 4);

        #pragma unroll
        for (int k = 0; k < 4; ++k) {
            float4 v = (k == 0) ? v0 : (k == 1) ? v1 : (k == 2) ? v2 : v3;

            float e0 = ex2f(arl * v.x);
            float e1 = ex2f(arl * v.y);
            float e2 = ex2f(arl * v.z);
            float e3 = ex2f(arl * v.w);
            acc.x += e0; acc.y += e1; acc.z += e2; acc.w += e3;

            float rsl;
            if (same) {
                rsl = (e0 + e1) + (e2 + e3);
            } else {
                rsl = ex2f(aql * v.x) + ex2f(aql * v.y)
                    + ex2f(aql * v.z) + ex2f(aql * v.w);
            }

            float mk = fmaxf(fmaxf(v.x, v.y), fmaxf(v.z, v.w));

            // shared 3-level butterfly over the 8-lane group (32 columns)
            #pragma unroll
            for (int o = 4; o > 0; o >>= 1) {
                rsl += __shfl_xor_sync(0xFFFFFFFFu, rsl, o);
                mk = fmaxf(mk, __shfl_xor_sync(0xFFFFFFFFu, mk, o));
            }

            // witness index: some lane's component equals mk exactly
            int idx = -1;
            if (v.x == mk) idx = l8;
            if (v.y == mk) idx = l8 + 1;
            if (v.z == mk) idx = l8 + 2;
            if (v.w == mk) idx = l8 + 3;
            if (idx >= 0) s_bi[(r + k) * NBLK + g] = (unsigned char)idx;

            if ((lane & 7) == 0) {
                s_bm[(r + k) * NBLK + g]   = mk;
                s_rs32[(r + k) * NBLK + g] = rsl;
            }
        }
    }
    __syncthreads();

    // partial column sums ([chunk][b][col])
    reinterpret_cast<float4*>(g_part + (size_t)c * (MAXB * Q) + (size_t)b * Q)[t] = acc;

    // finish row sums: thread t<64 sums 32 partials of row t (rotated, no conflicts)
    if (t < RCHUNK) {
        float s = 0.f;
        #pragma unroll
        for (int i = 0; i < NBLK; ++i)
            s += s_rs32[t * NBLK + ((i + t) & (NBLK - 1))];
        g_rs[b * R + c * RCHUNK + t] = s;
    }

    // block maxes (8 KB) + witness indices (2 KB)
    const size_t rowbase = (size_t)b * R + (size_t)c * RCHUNK;
    float4* gbm = reinterpret_cast<float4*>(g_bm + rowbase * NBLK);
    const float4* sb = reinterpret_cast<const float4*>(s_bm);
    gbm[t]       = sb[t];
    gbm[t + 256] = sb[t + 256];
    reinterpret_cast<uint2*>(g_bi + rowbase * NBLK)[t] =
        reinterpret_cast<const uint2*>(s_bi)[t];
}

// ---------------------------------------------------------------------------
// Kernel 2: Cref = log(colsum); per-32-column Cmin.
// ---------------------------------------------------------------------------
__global__ __launch_bounds__(256) void qatm_cred()
{
    const int b    = blockIdx.x >> 2;
    const int col  = ((blockIdx.x & 3) << 8) + threadIdx.x;
    const int lane = threadIdx.x & 31;

    const float* p = g_part + (size_t)b * Q + col;
    float s = 0.f;
    #pragma unroll 8
    for (int c = 0; c < NCHUNK; ++c)
        s += p[(size_t)c * (MAXB * Q)];

    float lg = __logf(s);
    g_creflog[b * Q + col] = lg;

    float mn = lg;
    #pragma unroll
    for (int o = 16; o > 0; o >>= 1)
        mn = fminf(mn, __shfl_xor_sync(0xFFFFFFFFu, mn, o));
    if (lane == 0)
        g_cmin[b * NBLK + (col >> 5)] = mn;
}

// ---------------------------------------------------------------------------
// Pass 2: warp per FOUR rows — all header loads issued independently up
// front (MLP ~8), joint survivor drain across the 4 masks.
// ---------------------------------------------------------------------------
__global__ __launch_bounds__(256) void qatm_p2(
    const float* __restrict__ x,
    const float* __restrict__ cr,
    const float* __restrict__ cq,
    float* __restrict__ out)
{
    const int wid  = threadIdx.x >> 5;
    const int lane = threadIdx.x & 31;
    const int row0 = (blockIdx.x * 8 + wid) * 4;
    const int b    = row0 >> 12;           // 4 consecutive rows share a batch

    const float cc = cr[0] + cq[0];
    const float* cl = g_creflog + (size_t)b * Q;

    // independent header loads for 4 rows
    const float cmin = __ldg(&g_cmin[b * NBLK + lane]);
    float bm0 = g_bm[(size_t)(row0 + 0) * NBLK + lane];
    float bm1 = g_bm[(size_t)(row0 + 1) * NBLK + lane];
    float bm2 = g_bm[(size_t)(row0 + 2) * NBLK + lane];
    float bm3 = g_bm[(size_t)(row0 + 3) * NBLK + lane];
    int bi0 = (int)g_bi[(size_t)(row0 + 0) * NBLK + lane];
    int bi1 = (int)g_bi[(size_t)(row0 + 1) * NBLK + lane];
    int bi2 = (int)g_bi[(size_t)(row0 + 2) * NBLK + lane];
    int bi3 = (int)g_bi[(size_t)(row0 + 3) * NBLK + lane];
    float rr = (lane < 4) ? __ldg(&g_rs[row0 + lane]) : 1.f;

    float cw0 = __ldg(cl + lane * 32 + bi0);
    float cw1 = __ldg(cl + lane * 32 + bi1);
    float cw2 = __ldg(cl + lane * 32 + bi2);
    float cw3 = __ldg(cl + lane * 32 + bi3);

    float ub0 = fmaf(cc, bm0, -cmin), v0 = fmaf(cc, bm0, -cw0);
    float ub1 = fmaf(cc, bm1, -cmin), v1 = fmaf(cc, bm1, -cw1);
    float ub2 = fmaf(cc, bm2, -cmin), v2 = fmaf(cc, bm2, -cw2);
    float ub3 = fmaf(cc, bm3, -cmin), v3 = fmaf(cc, bm3, -cw3);

    float m0 = v0, m1 = v1, m2 = v2, m3 = v3;
    #pragma unroll
    for (int o = 16; o > 0; o >>= 1) {
        m0 = fmaxf(m0, __shfl_xor_sync(0xFFFFFFFFu, m0, o));
        m1 = fmaxf(m1, __shfl_xor_sync(0xFFFFFFFFu, m1, o));
        m2 = fmaxf(m2, __shfl_xor_sync(0xFFFFFFFFu, m2, o));
        m3 = fmaxf(m3, __shfl_xor_sync(0xFFFFFFFFu, m3, o));
    }

    unsigned k0 = __ballot_sync(0xFFFFFFFFu, ub0 > m0);
    unsigned k1 = __ballot_sync(0xFFFFFFFFu, ub1 > m1);
    unsigned k2 = __ballot_sync(0xFFFFFFFFu, ub2 > m2);
    unsigned k3 = __ballot_sync(0xFFFFFFFFu, ub3 > m3);

    const float* px0 = x + (size_t)(row0 + 0) * Q;
    const float* px1 = x + (size_t)(row0 + 1) * Q;
    const float* px2 = x + (size_t)(row0 + 2) * Q;
    const float* px3 = x + (size_t)(row0 + 3) * Q;

    while (k0 | k1 | k2 | k3) {
        int j0 = -1, j1 = -1, j2 = -1, j3 = -1;
        if (k0) { j0 = __ffs(k0) - 1; k0 &= k0 - 1; }
        if (k1) { j1 = __ffs(k1) - 1; k1 &= k1 - 1; }
        if (k2) { j2 = __ffs(k2) - 1; k2 &= k2 - 1; }
        if (k3) { j3 = __ffs(k3) - 1; k3 &= k3 - 1; }

        // all loads issued before any consuming max (MLP up to 8)
        float a0 = (j0 >= 0) ? __ldcs(px0 + j0 * 32 + lane) : 0.f;
        float a1 = (j1 >= 0) ? __ldcs(px1 + j1 * 32 + lane) : 0.f;
        float a2 = (j2 >= 0) ? __ldcs(px2 + j2 * 32 + lane) : 0.f;
        float a3 = (j3 >= 0) ? __ldcs(px3 + j3 * 32 + lane) : 0.f;
        float c0 = (j0 >= 0) ? __ldg(cl + j0 * 32 + lane) : 0.f;
        float c1 = (j1 >= 0) ? __ldg(cl + j1 * 32 + lane) : 0.f;
        float c2 = (j2 >= 0) ? __ldg(cl + j2 * 32 + lane) : 0.f;
        float c3 = (j3 >= 0) ? __ldg(cl + j3 * 32 + lane) : 0.f;

        if (j0 >= 0) m0 = fmaxf(m0, fmaf(cc, a0, -c0));
        if (j1 >= 0) m1 = fmaxf(m1, fmaf(cc, a1, -c1));
        if (j2 >= 0) m2 = fmaxf(m2, fmaf(cc, a2, -c2));
        if (j3 >= 0) m3 = fmaxf(m3, fmaf(cc, a3, -c3));
    }

    #pragma unroll
    for (int o = 16; o > 0; o >>= 1) {
        m0 = fmaxf(m0, __shfl_xor_sync(0xFFFFFFFFu, m0, o));
        m1 = fmaxf(m1, __shfl_xor_sync(0xFFFFFFFFu, m1, o));
        m2 = fmaxf(m2, __shfl_xor_sync(0xFFFFFFFFu, m2, o));
        m3 = fmaxf(m3, __shfl_xor_sync(0xFFFFFFFFu, m3, o));
    }

    if (lane < 4) {
        float mm = (lane == 0) ? m0 : (lane == 1) ? m1 : (lane == 2) ? m2 : m3;
        out[row0 + lane] = __expf(0.5f * (mm - __logf(rr)));
    }
}

// ---------------------------------------------------------------------------
extern "C" void kernel_launch(void* const* d_in, const int* in_sizes, int n_in,
                              void* d_out, int out_size)
{
    const float* x  = (const float*)d_in[0];
    const float* cr = (const float*)d_in[1];
    const float* cq = (const float*)d_in[2];
    float* out = (float*)d_out;

    const int B = in_sizes[0] / (R * Q);   // 16

    qatm_pass1<<<B * NCHUNK, 256>>>(x, cr, cq);
    qatm_cred<<<B * 4, 256>>>();
    qatm_p2<<<B * R / 32, 256>>>(x, cr, cq, out);
}